// round 1
// baseline (speedup 1.0000x reference)
#include <cuda_runtime.h>

// Problem constants (fixed shapes: pred[8192,7,7,30], gt[8192,7,7,30])
#define NCH        30
#define TPB        128           // threads per block = cells per block
#define MAX_BLOCKS 4096          // 401408/128 = 3136 actual

// Per-block partial sums (no device allocation allowed -> device global)
__device__ float g_partials[MAX_BLOCKS];

__global__ __launch_bounds__(TPB)
void yolo_loss_main(const float* __restrict__ pred,
                    const float* __restrict__ gt,
                    int n_cells)
{
    __shared__ float s_pred[TPB * NCH];   // 15360 B
    __shared__ float s_gt  [TPB * NCH];   // 15360 B

    const int cell0 = blockIdx.x * TPB;            // first cell of this block
    const long long fbase = (long long)cell0 * NCH; // float offset (120B*cell0, 16B aligned)

    // ---- coalesced staging: 960 float4 per tensor ----
    const float4* p4 = reinterpret_cast<const float4*>(pred + fbase);
    const float4* g4 = reinterpret_cast<const float4*>(gt   + fbase);
    float4* sp4 = reinterpret_cast<float4*>(s_pred);
    float4* sg4 = reinterpret_cast<float4*>(s_gt);
    const int n4 = TPB * NCH / 4;                  // 960
    #pragma unroll 4
    for (int i = threadIdx.x; i < n4; i += TPB) {
        sp4[i] = p4[i];
        sg4[i] = g4[i];
    }
    __syncthreads();

    float loss = 0.0f;
    const int cell = cell0 + threadIdx.x;
    if (cell < n_cells) {
        const float* p = s_pred + threadIdx.x * NCH;
        const float* g = s_gt   + threadIdx.x * NCH;

        const float gx = g[0], gy = g[1], gw = g[2], gh = g[3];
        const float obj   = (g[4] > 0.0f) ? 1.0f : 0.0f;
        const float noobj = 1.0f - obj;

        const float pc0 = p[4];
        const float pc1 = p[9];

        // no-object confidence loss: gt conf is 0 on noobj cells, both boxes
        const float no_obj_term = noobj * (pc0 * pc0 + pc1 * pc1);

        // IoU of each predicted box vs gt box (corners = center +/- 0.5*GRID*wh)
        const float ghw = 3.5f * gw, ghh = 3.5f * gh;
        const float gx1 = gx - ghw, gx2 = gx + ghw;
        const float gy1 = gy - ghh, gy2 = gy + ghh;
        const float a2  = 49.0f * gw * gh;

        float iou[2];
        #pragma unroll
        for (int b = 0; b < 2; b++) {
            const float cx = p[b*5+0], cy = p[b*5+1];
            const float w  = p[b*5+2], h  = p[b*5+3];
            const float hw = 3.5f * w, hh = 3.5f * h;
            const float iw = fmaxf(fminf(cx + hw, gx2) - fmaxf(cx - hw, gx1), 0.0f);
            const float ih = fmaxf(fminf(cy + hh, gy2) - fmaxf(cy - hh, gy1), 0.0f);
            const float inter = iw * ih;
            const float a1 = 49.0f * w * h;
            iou[b] = inter / (a1 + a2 - inter);
        }

        // responsible box: argmax over 2 (first index wins ties, jnp semantics)
        const int   r       = (iou[1] > iou[0]) ? 1 : 0;
        const float max_iou = fmaxf(iou[0], iou[1]);
        const float* pr     = p + r * 5;
        const float pc_irr  = r ? pc0 : pc1;

        // coordinate loss (responsible box only)
        const float dx = pr[0] - gx;
        const float dy = pr[1] - gy;
        const float dw = sqrtf(pr[2]) - sqrtf(gw);
        const float dh = sqrtf(pr[3]) - sqrtf(gh);
        const float coord = dx*dx + dy*dy + dw*dw + dh*dh;

        // response (counted twice in total) & irresponse confidence losses
        const float dr = pr[4] - max_iou;
        const float resp_l   = dr * dr;
        const float irresp_l = pc_irr * pc_irr;

        // class loss over 20 channels
        float cls = 0.0f;
        #pragma unroll
        for (int c = 10; c < 30; c++) {
            const float d = p[c] - g[c];
            cls = fmaf(d, d, cls);
        }

        loss = obj * (5.0f * coord + 2.0f * resp_l + irresp_l + cls)
             + 0.5f * no_obj_term;
    }

    // ---- deterministic block reduction ----
    #pragma unroll
    for (int o = 16; o > 0; o >>= 1)
        loss += __shfl_down_sync(0xffffffffu, loss, o);

    __shared__ float s_warp[TPB / 32];
    const int lane = threadIdx.x & 31;
    const int wid  = threadIdx.x >> 5;
    if (lane == 0) s_warp[wid] = loss;
    __syncthreads();
    if (threadIdx.x == 0) {
        float v = s_warp[0] + s_warp[1] + s_warp[2] + s_warp[3];
        g_partials[blockIdx.x] = v;
    }
}

__global__ __launch_bounds__(1024)
void yolo_loss_reduce(float* __restrict__ out, int n_blocks, float inv_batch)
{
    // single block, fixed-order strided sum -> deterministic
    float v = 0.0f;
    for (int i = threadIdx.x; i < n_blocks; i += 1024)
        v += g_partials[i];

    #pragma unroll
    for (int o = 16; o > 0; o >>= 1)
        v += __shfl_down_sync(0xffffffffu, v, o);

    __shared__ float s_warp[32];
    const int lane = threadIdx.x & 31;
    const int wid  = threadIdx.x >> 5;
    if (lane == 0) s_warp[wid] = v;
    __syncthreads();
    if (threadIdx.x == 0) {
        float t = 0.0f;
        #pragma unroll
        for (int w = 0; w < 32; w++) t += s_warp[w];
        out[0] = t * inv_batch;
    }
}

extern "C" void kernel_launch(void* const* d_in, const int* in_sizes, int n_in,
                              void* d_out, int out_size)
{
    const float* pred = (const float*)d_in[0];
    const float* gt   = (const float*)d_in[1];
    float* out = (float*)d_out;

    const int n_cells = in_sizes[0] / NCH;          // 8192*49 = 401408
    const int n_blocks = (n_cells + TPB - 1) / TPB; // 3136
    const int batch = n_cells / 49;                 // 8192

    yolo_loss_main<<<n_blocks, TPB>>>(pred, gt, n_cells);
    yolo_loss_reduce<<<1, 1024>>>(out, n_blocks, 1.0f / (float)batch);
}